// round 7
// baseline (speedup 1.0000x reference)
#include <cuda_runtime.h>

// ---------------------------------------------------------------------------
// StepWiseMLPAutoEncoder — fp32, packed fma.rn.f32x2
// encoder: 128x64-tile GEMMs (512 thr, 2 blocks/SM)
// decoder: persistent kernel, per-batch-half barrier domains w/ tree arrivals,
//          coalesced step outputs into g_outT, final transpose
// ---------------------------------------------------------------------------

#define BATCH 64
#define SS    1024
#define TT    256
#define HH    64
#define EM    1056
#define DM    1056
#define KC    2048
#define KD1   1088
#define MROWS (BATCH*TT)
#define NBLK  132

typedef unsigned long long u64;

// scratch (device globals; padded for prefetch overshoot)
__device__ float g_xT[BATCH * TT * SS];
__device__ float g_h1[(size_t)MROWS * EM];
__device__ float g_ctrlT[TT * HH * BATCH + 1024];   // [T,H,B] k-major
__device__ float g_hdT[DM * BATCH + 1024];          // [K,B]
__device__ float g_outT[TT * SS * BATCH + 1024];    // [T,S,B]  (also = prev buffer)
__device__ float g_zero[SS * BATCH + 512];          // never written -> stays 0

// barrier state: 2 domains (batch halves), 4 leaves each, padded lines
__device__ unsigned g_leaf[2][4][32];
__device__ unsigned g_root[2][32];
__device__ unsigned g_gen2[2][32];

// ---- packed fp32x2 helpers -------------------------------------------------
__device__ __forceinline__ u64 pk2(float lo, float hi) {
    u64 r; asm("mov.b64 %0, {%1, %2};" : "=l"(r) : "f"(lo), "f"(hi)); return r;
}
__device__ __forceinline__ void fma2(u64& d, u64 a, u64 b) {
    asm("fma.rn.f32x2 %0, %1, %2, %0;" : "+l"(d) : "l"(a), "l"(b));
}
__device__ __forceinline__ void unpk2(u64 v, float& lo, float& hi) {
    asm("mov.b64 {%0, %1}, %2;" : "=f"(lo), "=f"(hi) : "l"(v));
}

// ---------------------------------------------------------------------------
// half-domain barrier: 66 blocks per domain, 4-leaf tree arrivals
// ---------------------------------------------------------------------------
__device__ __forceinline__ void half_sync(int h, int nt)
{
    __syncthreads();
    if (threadIdx.x == 0) {
        volatile unsigned* vgen = &g_gen2[h][0];
        unsigned my = *vgen;
        __threadfence();
        int l = nt & 3;
        unsigned cnt = (l < 2) ? 17u : 16u;     // 66 = 17+17+16+16
        if (atomicAdd(&g_leaf[h][l][0], 1u) == cnt - 1u) {
            atomicExch(&g_leaf[h][l][0], 0u);
            if (atomicAdd(&g_root[h][0], 1u) == 3u) {
                atomicExch(&g_root[h][0], 0u);
                __threadfence();
                atomicAdd((unsigned*)&g_gen2[h][0], 1u);
            }
        }
        while (*vgen == my) { }
        __threadfence();
    }
    __syncthreads();
}

// ---------------------------------------------------------------------------
// x[b,s,t] -> xT[b,t,s]
// ---------------------------------------------------------------------------
__global__ void transpose_x_kernel(const float* __restrict__ x)
{
    __shared__ float tile[32][33];
    int b  = blockIdx.z;
    int t0 = blockIdx.x * 32;
    int s0 = blockIdx.y * 32;
    const float* xb  = x    + (size_t)b * SS * TT;
    float*       xTb = g_xT + (size_t)b * TT * SS;
    int tx = threadIdx.x, ty = threadIdx.y;
#pragma unroll
    for (int j = 0; j < 32; j += 8)
        tile[ty + j][tx] = xb[(s0 + ty + j) * TT + t0 + tx];
    __syncthreads();
#pragma unroll
    for (int j = 0; j < 32; j += 8)
        xTb[(t0 + ty + j) * SS + s0 + tx] = tile[tx][ty + j];
}

// ---------------------------------------------------------------------------
// final: g_outT[t,s,b] -> out[b,s,t]
// ---------------------------------------------------------------------------
__global__ void transpose_out_kernel(float* __restrict__ out)
{
    __shared__ float tile[32][33];
    int t0 = blockIdx.x * 32;
    int b0 = blockIdx.y * 32;
    int s  = blockIdx.z;
    int tx = threadIdx.x, ty = threadIdx.y;
#pragma unroll
    for (int j = 0; j < 32; j += 8)
        tile[ty + j][tx] = g_outT[(size_t)(t0 + ty + j) * SS * BATCH + s * BATCH + b0 + tx];
    __syncthreads();
#pragma unroll
    for (int j = 0; j < 32; j += 8)
        out[(size_t)(b0 + ty + j) * SS * TT + (size_t)s * TT + t0 + tx] = tile[tx][ty + j];
}

// ---------------------------------------------------------------------------
// Encoder GEMM, 128x64 tile, BK=16, 512 threads, 4m x 4n per thread, f32x2.
// MODE 0: A = comb (from g_xT), C = relu(A@We1+be1) -> g_h1
// MODE 1: A = g_h1,             C = A@We2+be2       -> g_ctrlT
// ---------------------------------------------------------------------------
template<int MODE>
__global__ __launch_bounds__(512, 2) void enc_gemm_kernel(
    const float* __restrict__ Bmat, const float* __restrict__ bias)
{
    constexpr int N = (MODE == 0) ? EM : HH;
    constexpr int K = (MODE == 0) ? KC : EM;

    __shared__ float As[16][132];   // [k][m], padded
    __shared__ float Bs[16][68];    // [k][n], padded

    int tid  = threadIdx.x;
    int arow = tid >> 2;            // 0..127
    int acol = (tid & 3) * 4;
    int bk   = tid >> 5;            // 0..15
    int bn   = (tid & 31) * 2;      // 0..62
    int tn   = tid & 15;
    int tm   = tid >> 4;            // 0..31
    int n0   = blockIdx.x * 64;
    int r0   = blockIdx.y * 128;

    u64 acc2[4][2];
#pragma unroll
    for (int i = 0; i < 4; i++) { acc2[i][0] = 0ULL; acc2[i][1] = 0ULL; }

    int r = r0 + arow;
    const float* aprev = nullptr;
    const float* acur  = nullptr;
    if (MODE == 0) {
        int bb = r >> 8;
        int t  = r & 255;
        acur  = g_xT + ((size_t)((bb << 8) + t)) * SS;
        aprev = (t > 0) ? (acur - SS) : nullptr;
    } else {
        acur = g_h1 + (size_t)r * K;
    }

    for (int kc = 0; kc < K; kc += 16) {
        // A tile: one float4 per thread
        float4 av = make_float4(0.f, 0.f, 0.f, 0.f);
        int kg = kc + acol;
        if (MODE == 0) {
            if (kg < SS) {
                if (aprev) av = *(const float4*)(aprev + kg);
            } else {
                av = *(const float4*)(acur + kg - SS);
            }
        } else {
            av = *(const float4*)(acur + kg);
        }
        As[acol + 0][arow] = av.x;
        As[acol + 1][arow] = av.y;
        As[acol + 2][arow] = av.z;
        As[acol + 3][arow] = av.w;

        // B tile: one float2 per thread
        {
            int ng = n0 + bn;
            float2 bv = make_float2(0.f, 0.f);
            if (ng < N) bv = *(const float2*)&Bmat[(size_t)(kc + bk) * N + ng];
            Bs[bk][bn]     = bv.x;
            Bs[bk][bn + 1] = bv.y;
        }
        __syncthreads();

#pragma unroll
        for (int kk = 0; kk < 16; kk++) {
            float4 a4 = *(const float4*)&As[kk][tm * 4];
            ulonglong2 b2 = *(const ulonglong2*)&Bs[kk][tn * 4];
            u64 d0 = pk2(a4.x, a4.x);
            u64 d1 = pk2(a4.y, a4.y);
            u64 d2 = pk2(a4.z, a4.z);
            u64 d3 = pk2(a4.w, a4.w);
            fma2(acc2[0][0], d0, b2.x); fma2(acc2[0][1], d0, b2.y);
            fma2(acc2[1][0], d1, b2.x); fma2(acc2[1][1], d1, b2.y);
            fma2(acc2[2][0], d2, b2.x); fma2(acc2[2][1], d2, b2.y);
            fma2(acc2[3][0], d3, b2.x); fma2(acc2[3][1], d3, b2.y);
        }
        __syncthreads();
    }

#pragma unroll
    for (int i = 0; i < 4; i++) {
        float c[4];
        unpk2(acc2[i][0], c[0], c[1]);
        unpk2(acc2[i][1], c[2], c[3]);
        int rr = r0 + tm * 4 + i;
#pragma unroll
        for (int j = 0; j < 4; j++) {
            int ng = n0 + tn * 4 + j;
            if (ng < N) {
                float v = c[j] + bias[ng];
                if (MODE == 0) {
                    g_h1[(size_t)rr * EM + ng] = fmaxf(v, 0.f);
                } else {
                    int bb = rr >> 8;
                    int tt = rr & 255;
                    g_ctrlT[(tt * HH + ng) * BATCH + bb] = v;
                }
            }
        }
    }
}

// ---------------------------------------------------------------------------
// Persistent decoder.
// 132 blocks x 512 thr. Block = (n-tile nt = bid>>1, batch-half mh = bid&1):
// 16 n-cols x 32 m-rows. 16 warps = 16 k-split groups (1 warp each).
// Thread: 1 m-row, 16 n (8 f32x2 accumulators). Weights SMEM k-row-major.
// Two independent barrier domains (one per batch half).
// ---------------------------------------------------------------------------
#define DEC_SMEM ((KD1*16 + DM*16 + 16*16*32) * 4)

__device__ __forceinline__ void dec_seg(
    u64 acc[8], const float* __restrict__ src, const float* __restrict__ Ws,
    int k0, int nk, int moff)
{
    const float* s = src + moff;
    const ulonglong2* wp = (const ulonglong2*)(Ws + k0 * 16);
    float av[4];
#pragma unroll
    for (int kk = 0; kk < 4; kk++) av[kk] = s[64 * kk];

    for (int i = 0; i < nk; i += 4) {
        s += 256;
        float nv[4];
#pragma unroll
        for (int kk = 0; kk < 4; kk++) nv[kk] = s[64 * kk];  // prefetch (padded)
#pragma unroll
        for (int kk = 0; kk < 4; kk++) {
            u64 ad = pk2(av[kk], av[kk]);
            ulonglong2 w0 = wp[0], w1 = wp[1], w2 = wp[2], w3 = wp[3];
            wp += 4;
            fma2(acc[0], ad, w0.x); fma2(acc[1], ad, w0.y);
            fma2(acc[2], ad, w1.x); fma2(acc[3], ad, w1.y);
            fma2(acc[4], ad, w2.x); fma2(acc[5], ad, w2.y);
            fma2(acc[6], ad, w3.x); fma2(acc[7], ad, w3.y);
        }
#pragma unroll
        for (int kk = 0; kk < 4; kk++) av[kk] = nv[kk];
    }
}

__global__ __launch_bounds__(512) void dec_persistent_kernel(
    const float* __restrict__ Wd1, const float* __restrict__ bd1,
    const float* __restrict__ Wd2, const float* __restrict__ bd2)
{
    extern __shared__ float sm[];
    float* Ws1 = sm;                        // [KD1][16]
    float* Ws2 = sm + KD1 * 16;             // [DM][16]
    float* red = sm + (KD1 + DM) * 16;      // [16g][16n][32m]

    int tid = threadIdx.x;
    int bid = blockIdx.x;
    int nt  = bid >> 1;          // n-tile 0..65
    int mh  = bid & 1;           // batch half
    int n0  = nt * 16;

    // one-time: cache weight slices k-row-major [k][16]
    for (int i = tid; i < 16 * KD1; i += 512) {
        int k = i >> 4, n = i & 15;
        Ws1[i] = Wd1[(size_t)k * DM + n0 + n];
    }
    if (nt < 64) {
        for (int i = tid; i < 16 * DM; i += 512) {
            int k = i >> 4, n = i & 15;
            Ws2[i] = Wd2[(size_t)k * SS + n0 + n];
        }
    }

    int g    = tid >> 5;             // k-split group = warp 0..15
    int lane = tid & 31;
    int moff = mh * 32 + lane;       // global batch row
    int en   = tid >> 5;             // epilogue n 0..15
    int em   = tid & 31;             // epilogue m 0..31

    float bv1 = bd1[n0 + en];
    float bv2 = (nt < 64) ? bd2[n0 + en] : 0.f;

    // layer1 k-segments: 16 x 68 = 1088 (g0: 64 ctrl + 4 prev)
    int kb1 = g * 68;
    // layer2 k-segments: 8 x 68 + 8 x 64 = 1056
    int kb2 = (g < 8) ? g * 68 : 544 + (g - 8) * 64;
    int nk2 = (g < 8) ? 68 : 64;

    for (int t = 0; t < TT; t++) {
        const float* prevT = (t == 0) ? g_zero
                                      : g_outT + (size_t)(t - 1) * SS * BATCH;
        const float* ctrl_base = g_ctrlT + t * HH * BATCH;

        // ---- layer 1: g_hdT = relu([ctrl_t | prev] @ Wd1 + bd1), K=1088
        {
            u64 acc[8] = {};
            if (g == 0) {
                dec_seg(acc, ctrl_base, Ws1, 0, 64, moff);   // k 0..63 (ctrl)
                dec_seg(acc, prevT, Ws1, 64, 4, moff);       // k 64..67
            } else {
                dec_seg(acc, prevT + (kb1 - HH) * 64, Ws1, kb1, 68, moff);
            }
#pragma unroll
            for (int p = 0; p < 8; p++) {
                float lo, hi; unpk2(acc[p], lo, hi);
                red[(g * 16 + 2 * p) * 32 + lane]     = lo;
                red[(g * 16 + 2 * p + 1) * 32 + lane] = hi;
            }
            __syncthreads();

            float v = bv1;
#pragma unroll
            for (int gg = 0; gg < 16; gg++)
                v += red[(gg * 16 + en) * 32 + em];
            g_hdT[(n0 + en) * 64 + mh * 32 + em] = fmaxf(v, 0.f);
        }
        half_sync(mh, nt);

        // ---- layer 2: out_t = g_hd @ Wd2 + bd2, K=1056
        if (nt < 64) {
            u64 acc[8] = {};
            dec_seg(acc, g_hdT + kb2 * 64, Ws2, kb2, nk2, moff);
#pragma unroll
            for (int p = 0; p < 8; p++) {
                float lo, hi; unpk2(acc[p], lo, hi);
                red[(g * 16 + 2 * p) * 32 + lane]     = lo;
                red[(g * 16 + 2 * p + 1) * 32 + lane] = hi;
            }
            __syncthreads();

            float v = bv2;
#pragma unroll
            for (int gg = 0; gg < 16; gg++)
                v += red[(gg * 16 + en) * 32 + em];
            int s = n0 + en;
            g_outT[(size_t)t * SS * BATCH + s * BATCH + mh * 32 + em] = v;
        }
        half_sync(mh, nt);
    }
}

// ---------------------------------------------------------------------------
extern "C" void kernel_launch(void* const* d_in, const int* in_sizes, int n_in,
                              void* d_out, int out_size)
{
    const float* x   = (const float*)d_in[0];
    const float* We1 = (const float*)d_in[1];
    const float* be1 = (const float*)d_in[2];
    const float* We2 = (const float*)d_in[3];
    const float* be2 = (const float*)d_in[4];
    const float* Wd1 = (const float*)d_in[5];
    const float* bd1 = (const float*)d_in[6];
    const float* Wd2 = (const float*)d_in[7];
    const float* bd2 = (const float*)d_in[8];
    float* out = (float*)d_out;

    cudaFuncSetAttribute(dec_persistent_kernel,
                         cudaFuncAttributeMaxDynamicSharedMemorySize, DEC_SMEM);

    // encoder (parallel)
    transpose_x_kernel<<<dim3(TT / 32, SS / 32, BATCH), dim3(32, 8)>>>(x);
    enc_gemm_kernel<0><<<dim3((EM + 63) / 64, MROWS / 128), 512>>>(We1, be1);
    enc_gemm_kernel<1><<<dim3(1, MROWS / 128), 512>>>(We2, be2);

    // decoder: persistent kernel over all 256 steps
    dec_persistent_kernel<<<NBLK, 512, DEC_SMEM>>>(Wd1, bd1, Wd2, bd2);

    // final layout fix: g_outT[t,s,b] -> out[b,s,t]
    transpose_out_kernel<<<dim3(TT / 32, BATCH / 32, SS), dim3(32, 8)>>>(out);
}